// round 15
// baseline (speedup 1.0000x reference)
#include <cuda_runtime.h>
#include <cuda_bf16.h>
#include <cuda_fp16.h>
#include <cstdint>

#define B_ 512
#define T_ 256
#define C_ 384
#define H_ 64
#define SCALE_F 19.595917942265423f
#define QK_SCALE (SCALE_F * 1.4426950408889634f)   // fold log2(e) -> use ex2

// scratch: q,k,v projections [B,T,H] fp32
__device__ float g_q[B_ * T_ * H_];
__device__ float g_k[B_ * T_ * H_];
__device__ float g_v[B_ * T_ * H_];
// W in fragment-linear layout: [half(2)][chunk(6)][hl(2)][nt(12)][ks(4)][lane(32)][reg(2)] b32
__device__ uint32_t g_Wfrag32[73728];
// per-batch proj completion counters (zeroed by split_w each launch)
__device__ int g_cnt[B_];

__device__ __forceinline__ uint32_t smem_u32(const void* p) {
    uint32_t a;
    asm("{ .reg .u64 t; cvta.to.shared.u64 t, %1; cvt.u32.u64 %0, t; }"
        : "=r"(a) : "l"(p));
    return a;
}
#define CP_ASYNC16(dst_u32, src_ptr) \
    asm volatile("cp.async.ca.shared.global [%0], [%1], 16;" \
                 :: "r"(dst_u32), "l"(src_ptr) : "memory")
#define CP_COMMIT()  asm volatile("cp.async.commit_group;" ::: "memory")
#define CP_WAIT0()   asm volatile("cp.async.wait_group 0;" ::: "memory")

__device__ __forceinline__ void hmma_bf16(float* c, const uint32_t* a, const uint32_t* b) {
    asm volatile("mma.sync.aligned.m16n8k16.row.col.f32.bf16.bf16.f32 "
        "{%0,%1,%2,%3},{%4,%5,%6,%7},{%8,%9},{%0,%1,%2,%3};"
        : "+f"(c[0]), "+f"(c[1]), "+f"(c[2]), "+f"(c[3])
        : "r"(a[0]), "r"(a[1]), "r"(a[2]), "r"(a[3]), "r"(b[0]), "r"(b[1]));
}
__device__ __forceinline__ void hmma_f16(float* c, const uint32_t* a, const uint32_t* b) {
    asm volatile("mma.sync.aligned.m16n8k16.row.col.f32.f16.f16.f32 "
        "{%0,%1,%2,%3},{%4,%5,%6,%7},{%8,%9},{%0,%1,%2,%3};"
        : "+f"(c[0]), "+f"(c[1]), "+f"(c[2]), "+f"(c[3])
        : "r"(a[0]), "r"(a[1]), "r"(a[2]), "r"(a[3]), "r"(b[0]), "r"(b[1]));
}
__device__ __forceinline__ float ex2f(float x) {
    float y;
    asm("ex2.approx.f32 %0, %1;" : "=f"(y) : "f"(x));
    return y;
}
__device__ __forceinline__ uint32_t h2exp2(uint32_t x) {
    uint32_t y;
    asm("ex2.approx.f16x2 %0, %1;" : "=r"(y) : "r"(x));
    return y;
}
// hi/lo split, bf16 (round-5 exact form)
__device__ __forceinline__ void pack_hl(float x, float y, uint32_t& hi, uint32_t& lo) {
    __nv_bfloat16 hx = __float2bfloat16(x), hy = __float2bfloat16(y);
    __nv_bfloat16 lx = __float2bfloat16(x - __bfloat162float(hx));
    __nv_bfloat16 ly = __float2bfloat16(y - __bfloat162float(hy));
    __nv_bfloat162 h = __halves2bfloat162(hx, hy);
    __nv_bfloat162 l = __halves2bfloat162(lx, ly);
    hi = *reinterpret_cast<uint32_t*>(&h);
    lo = *reinterpret_cast<uint32_t*>(&l);
}
__device__ __forceinline__ uint32_t pack_f16(float x, float y) {
    __half2 h = __floats2half2_rn(x, y);
    return *reinterpret_cast<uint32_t*>(&h);
}

// ======================= W split + counter zero ===========================
__global__ void split_w_kernel(const float* __restrict__ Wq,
                               const float* __restrict__ Wk,
                               const float* __restrict__ Wv) {
    if (blockIdx.x == 0) {                    // zero per-batch counters
        g_cnt[threadIdx.x] = 0;
        g_cnt[threadIdx.x + 256] = 0;
    }
    int t = blockIdx.x * 256 + threadIdx.x;   // 36864 = 192 n x 192 k-pairs
    if (t >= 192 * 192) return;
    int n  = t / 192;
    int kp = t - n * 192;
    int k0 = kp * 2;
    int mat = n >> 6, col = n & 63;
    const float* W = (mat == 0) ? Wq : (mat == 1 ? Wk : Wv);
    float v0 = W[(size_t)k0 * 64 + col];
    float v1 = W[(size_t)(k0 + 1) * 64 + col];
    uint32_t hp, lp;
    pack_hl(v0, v1, hp, lp);

    int half  = (n >= 96) ? 1 : 0;
    int nl    = n - 96 * half;
    int nt    = nl >> 3;
    int chunk = k0 >> 6;
    int kc    = k0 & 63;
    int ks    = kc >> 4;
    int kk    = kc & 15;
    int lane  = ((nl & 7) << 2) | ((kk >> 1) & 3);
    int reg   = kk >> 3;
    int idx0 = (((((half * 6 + chunk) * 2 + 0) * 12 + nt) * 4 + ks) * 32 + lane) * 2 + reg;
    int idx1 = (((((half * 6 + chunk) * 2 + 1) * 12 + nt) * 4 + ks) * 32 + lane) * 2 + reg;
    g_Wfrag32[idx0] = hp;
    g_Wfrag32[idx1] = lp;
}

// ======================= fused proj + attention ===========================
// Each CTA: round-12 proj tile (b = mtile*2 + half), then release-fence +
// atomicAdd on its batch counter; the 4th finisher runs that batch's attn
// (round-14 form: QK bf16 3-pass, PV fp16 + ones column, h2exp) in-place.
#define SA_B32 8192
#define SB_B32 6144
#define ATTK_B32 8192
#define ATTV_B32 9216
#define FUSED_SMEM ((2 * ATTK_B32 + ATTV_B32) * 4)   // 102400 B (>= proj 57344)

__global__ __launch_bounds__(256, 2)
void fused_kernel(const float* __restrict__ x, float* out) {
    extern __shared__ uint32_t sm32[];
    __shared__ int s_doattn;

    const int b    = blockIdx.x;
    const int tid  = threadIdx.x;
    const int lane = tid & 31;
    const int wid  = tid >> 5;

    // ======================= proj part (round-12) =======================
    {
        uint32_t* sA = sm32;
        uint32_t* sB = sm32 + SA_B32;
        const uint32_t sB_smem = smem_u32(sB);
        const int wm   = wid >> 2;
        const int wn   = wid & 3;
        const int mtile = b >> 1;
        const int half  = b & 1;
        const int row0  = mtile * 128;

        float acc[4][3][4];
        #pragma unroll
        for (int mt = 0; mt < 4; ++mt)
            #pragma unroll
            for (int nt = 0; nt < 3; ++nt)
                #pragma unroll
                for (int e = 0; e < 4; ++e) acc[mt][nt][e] = 0.0f;

        #pragma unroll 1
        for (int c = 0; c < 6; ++c) {
            __syncthreads();
            {
                const uint32_t* src = g_Wfrag32 + (size_t)(half * 6 + c) * SB_B32;
                #pragma unroll
                for (int j = 0; j < 6; ++j) {
                    int i = tid + j * 256;
                    CP_ASYNC16(sB_smem + i * 16, src + i * 4);
                }
                CP_COMMIT();
            }
            #pragma unroll
            for (int j = 0; j < 8; ++j) {
                int idx = tid + j * 256;
                int m  = idx >> 4;
                int c4 = idx & 15;
                float4 v = *reinterpret_cast<const float4*>(
                    x + (size_t)(row0 + m) * C_ + c * 64 + c4 * 4);
                uint32_t hp0, lp0, hp1, lp1;
                pack_hl(v.x, v.y, hp0, lp0);
                pack_hl(v.z, v.w, hp1, lp1);
                int mt    = m >> 4;
                int ks    = c4 >> 2;
                int lane0 = ((m & 7) << 2) | (2 * (c4 & 1));
                int reg   = (c4 & 2) | ((m & 8) >> 3);
                int b0 = ((mt * 4 + ks) * 32 + lane0) * 4 + reg;
                sA[b0]                  = hp0;
                sA[b0 + 4]              = hp1;
                sA[b0 + SA_B32 / 2]     = lp0;
                sA[b0 + SA_B32 / 2 + 4] = lp1;
            }
            CP_WAIT0();
            __syncthreads();

            #pragma unroll
            for (int ks = 0; ks < 4; ++ks) {
                uint32_t af[2][4][4];
                uint32_t bf[2][3][2];
                #pragma unroll
                for (int hl = 0; hl < 2; ++hl)
                    #pragma unroll
                    for (int mt = 0; mt < 4; ++mt) {
                        const uint32_t* p = sA + ((((hl * 8) + wm * 4 + mt) * 4 + ks) * 32 + lane) * 4;
                        uint4 q = *reinterpret_cast<const uint4*>(p);
                        af[hl][mt][0] = q.x; af[hl][mt][1] = q.y;
                        af[hl][mt][2] = q.z; af[hl][mt][3] = q.w;
                    }
                #pragma unroll
                for (int hl = 0; hl < 2; ++hl)
                    #pragma unroll
                    for (int nt = 0; nt < 3; ++nt) {
                        const uint32_t* p = sB + ((((hl * 12) + wn * 3 + nt) * 4 + ks) * 32 + lane) * 2;
                        uint2 q = *reinterpret_cast<const uint2*>(p);
                        bf[hl][nt][0] = q.x; bf[hl][nt][1] = q.y;
                    }
                #pragma unroll
                for (int mt = 0; mt < 4; ++mt)
                    #pragma unroll
                    for (int nt = 0; nt < 3; ++nt)
                        hmma_bf16(acc[mt][nt], af[0][mt], bf[0][nt]);
                #pragma unroll
                for (int mt = 0; mt < 4; ++mt)
                    #pragma unroll
                    for (int nt = 0; nt < 3; ++nt)
                        hmma_bf16(acc[mt][nt], af[0][mt], bf[1][nt]);
                #pragma unroll
                for (int mt = 0; mt < 4; ++mt)
                    #pragma unroll
                    for (int nt = 0; nt < 3; ++nt)
                        hmma_bf16(acc[mt][nt], af[1][mt], bf[0][nt]);
            }
        }

        #pragma unroll
        for (int mt = 0; mt < 4; ++mt) {
            #pragma unroll
            for (int nt = 0; nt < 3; ++nt) {
                int n0  = half * 96 + wn * 24 + nt * 8;
                int mat = n0 >> 6;
                int col = (n0 & 63) + (lane & 3) * 2;
                float* O = (mat == 0) ? g_q : (mat == 1 ? g_k : g_v);
                int grow = row0 + wm * 64 + mt * 16 + (lane >> 2);
                *reinterpret_cast<float2*>(&O[(size_t)grow * 64 + col]) =
                    make_float2(acc[mt][nt][0], acc[mt][nt][1]);
                *reinterpret_cast<float2*>(&O[(size_t)(grow + 8) * 64 + col]) =
                    make_float2(acc[mt][nt][2], acc[mt][nt][3]);
            }
        }
    }

    // ============== release + last-finisher election ==============
    __syncthreads();                   // all proj stores program-ordered
    if (tid == 0) {
        __threadfence();               // release (cumulative: covers CTA's stores)
        int old = atomicAdd(&g_cnt[b >> 2], 1);
        s_doattn = (old == 3) ? 1 : 0;
    }
    __syncthreads();
    if (!s_doattn) return;
    __threadfence();                   // acquire before reading peers' q/k/v

    // ======================= attn part (round-14) =======================
    {
        uint32_t* sKhi = sm32;
        uint32_t* sKlo = sm32 + ATTK_B32;
        uint32_t* sV   = sm32 + 2 * ATTK_B32;

        const int bb = b >> 2;
        const int w  = wid;            // 0..7
        const float* qp = g_q + (size_t)bb * T_ * H_;
        const float* kp = g_k + (size_t)bb * T_ * H_;
        const float* vp = g_v + (size_t)bb * T_ * H_;
        float* outp = out + (size_t)bb * T_ * H_;

        // ---- prep: K -> bf16 hi/lo, V -> fp16 (+ones tile) ----
        #pragma unroll 4
        for (int it = 0; it < 32; ++it) {
            int slot = w + it * 8;
            int reg = slot & 1, nt = (slot >> 1) & 7, ks = (slot >> 4) & 3, j = slot >> 6;
            int addr = (slot >> 1) * 64 + lane * 2 + reg;
            {
                int s = j * 64 + nt * 8 + (lane >> 2);
                int h = ks * 16 + (lane & 3) * 2 + reg * 8;
                float2 kv = *reinterpret_cast<const float2*>(kp + s * 64 + h);
                uint32_t hp, lp;
                pack_hl(kv.x, kv.y, hp, lp);
                sKhi[addr] = hp; sKlo[addr] = lp;
            }
            {
                int n  = nt * 8 + (lane >> 2);
                int s0 = j * 64 + ks * 16 + (lane & 3) * 2 + reg * 8;
                float v0 = vp[s0 * 64 + n];
                float v1 = vp[(s0 + 1) * 64 + n];
                int jk = j * 4 + ks;
                sV[(jk * 9 + nt) * 64 + lane * 2 + reg] = pack_f16(v0, v1);
            }
        }
        #pragma unroll
        for (int i = tid; i < 1024; i += 256) {
            int jk = i >> 6;
            sV[(jk * 9 + 8) * 64 + (i & 63)] = 0x3C003C00u;   // (1.0h, 1.0h)
        }
        __syncthreads();

        #pragma unroll 1
        for (int hf = 0; hf < 2; ++hf) {
            const int t = hf ? (15 - w) : w;
            const int jmax = t >> 2;
            const int r0 = t * 16 + (lane >> 2);

            uint32_t qh[4][4], ql[4][4];
            #pragma unroll
            for (int ks = 0; ks < 4; ++ks) {
                int k0 = ks * 16 + (lane & 3) * 2;
                float2 v00 = *reinterpret_cast<const float2*>(qp + r0 * 64 + k0);
                float2 v10 = *reinterpret_cast<const float2*>(qp + (r0 + 8) * 64 + k0);
                float2 v01 = *reinterpret_cast<const float2*>(qp + r0 * 64 + k0 + 8);
                float2 v11 = *reinterpret_cast<const float2*>(qp + (r0 + 8) * 64 + k0 + 8);
                pack_hl(v00.x * QK_SCALE, v00.y * QK_SCALE, qh[ks][0], ql[ks][0]);
                pack_hl(v10.x * QK_SCALE, v10.y * QK_SCALE, qh[ks][1], ql[ks][1]);
                pack_hl(v01.x * QK_SCALE, v01.y * QK_SCALE, qh[ks][2], ql[ks][2]);
                pack_hl(v11.x * QK_SCALE, v11.y * QK_SCALE, qh[ks][3], ql[ks][3]);
            }

            float o[9][4];
            #pragma unroll
            for (int nt = 0; nt < 9; ++nt)
                #pragma unroll
                for (int e = 0; e < 4; ++e) o[nt][e] = 0.0f;
            float m0 = -1.0e30f, m1 = -1.0e30f;

            #pragma unroll 1
            for (int j = 0; j <= jmax; ++j) {
                float s[8][4];
                #pragma unroll
                for (int nt = 0; nt < 8; ++nt)
                    #pragma unroll
                    for (int e = 0; e < 4; ++e) s[nt][e] = 0.0f;
                #pragma unroll
                for (int ks = 0; ks < 4; ++ks) {
                    const uint2* kh = reinterpret_cast<const uint2*>(sKhi) + ((j * 4 + ks) * 8) * 32 + lane;
                    const uint2* kl = reinterpret_cast<const uint2*>(sKlo) + ((j * 4 + ks) * 8) * 32 + lane;
                    #pragma unroll
                    for (int nt = 0; nt < 8; ++nt) {
                        uint2 bh2 = kh[nt * 32], bl2 = kl[nt * 32];
                        uint32_t bh[2] = {bh2.x, bh2.y};
                        uint32_t bl[2] = {bl2.x, bl2.y};
                        hmma_bf16(s[nt], qh[ks], bh);
                        hmma_bf16(s[nt], qh[ks], bl);
                        hmma_bf16(s[nt], ql[ks], bh);
                    }
                }
                if (j == jmax) {
                    int cb = 64 * j + (lane & 3) * 2;
                    #pragma unroll
                    for (int nt = 0; nt < 8; ++nt) {
                        int c = cb + nt * 8;
                        if (c > r0)         s[nt][0] = -1.0e30f;
                        if (c + 1 > r0)     s[nt][1] = -1.0e30f;
                        if (c > r0 + 8)     s[nt][2] = -1.0e30f;
                        if (c + 1 > r0 + 8) s[nt][3] = -1.0e30f;
                    }
                }
                float bm0 = -1.0e30f, bm1 = -1.0e30f;
                #pragma unroll
                for (int nt = 0; nt < 8; ++nt) {
                    bm0 = fmaxf(bm0, fmaxf(s[nt][0], s[nt][1]));
                    bm1 = fmaxf(bm1, fmaxf(s[nt][2], s[nt][3]));
                }
                bm0 = fmaxf(bm0, __shfl_xor_sync(0xffffffffu, bm0, 1));
                bm0 = fmaxf(bm0, __shfl_xor_sync(0xffffffffu, bm0, 2));
                bm1 = fmaxf(bm1, __shfl_xor_sync(0xffffffffu, bm1, 1));
                bm1 = fmaxf(bm1, __shfl_xor_sync(0xffffffffu, bm1, 2));
                float mn0 = fmaxf(m0, bm0), mn1 = fmaxf(m1, bm1);
                float sc0 = ex2f(m0 - mn0), sc1 = ex2f(m1 - mn1);
                m0 = mn0; m1 = mn1;
                uint32_t p2[8][2];
                #pragma unroll
                for (int nt = 0; nt < 8; ++nt) {
                    p2[nt][0] = h2exp2(pack_f16(s[nt][0] - mn0, s[nt][1] - mn0));
                    p2[nt][1] = h2exp2(pack_f16(s[nt][2] - mn1, s[nt][3] - mn1));
                }
                #pragma unroll
                for (int nt = 0; nt < 9; ++nt) {
                    o[nt][0] *= sc0; o[nt][1] *= sc0;
                    o[nt][2] *= sc1; o[nt][3] *= sc1;
                }
                #pragma unroll
                for (int kk = 0; kk < 4; ++kk) {
                    uint32_t pa[4];
                    pa[0] = p2[2 * kk][0];
                    pa[1] = p2[2 * kk][1];
                    pa[2] = p2[2 * kk + 1][0];
                    pa[3] = p2[2 * kk + 1][1];
                    const uint2* vh = reinterpret_cast<const uint2*>(sV) + ((j * 4 + kk) * 9) * 32 + lane;
                    #pragma unroll
                    for (int nt = 0; nt < 9; ++nt) {
                        uint2 bh2 = vh[nt * 32];
                        uint32_t bh[2] = {bh2.x, bh2.y};
                        hmma_f16(o[nt], pa, bh);
                    }
                }
            }

            float inv0 = 1.0f / o[8][0], inv1 = 1.0f / o[8][2];
            #pragma unroll
            for (int nt = 0; nt < 8; ++nt) {
                int col = nt * 8 + (lane & 3) * 2;
                *reinterpret_cast<float2*>(outp + r0 * 64 + col) =
                    make_float2(o[nt][0] * inv0, o[nt][1] * inv0);
                *reinterpret_cast<float2*>(outp + (r0 + 8) * 64 + col) =
                    make_float2(o[nt][2] * inv1, o[nt][3] * inv1);
            }
        }
    }
}

// ---------------------------------------------------------------------------
extern "C" void kernel_launch(void* const* d_in, const int* in_sizes, int n_in,
                              void* d_out, int out_size) {
    const float* x  = (const float*)d_in[0];
    const float* Wq = (const float*)d_in[1];
    const float* Wk = (const float*)d_in[2];
    const float* Wv = (const float*)d_in[3];
    float* out = (float*)d_out;

    cudaFuncSetAttribute(fused_kernel, cudaFuncAttributeMaxDynamicSharedMemorySize, FUSED_SMEM);

    split_w_kernel<<<144, 256>>>(Wq, Wk, Wv);
    fused_kernel<<<2048, 256, FUSED_SMEM>>>(x, out);
}

// round 16
// speedup vs baseline: 1.1466x; 1.1466x over previous
#include <cuda_runtime.h>
#include <cuda_bf16.h>
#include <cuda_fp16.h>
#include <cstdint>

#define B_ 512
#define T_ 256
#define C_ 384
#define H_ 64
#define SCALE_F 19.595917942265423f
#define QK_SCALE (SCALE_F * 1.4426950408889634f)   // fold log2(e) -> use ex2

// scratch: q,k,v projections [B,T,H] fp32
__device__ float g_q[B_ * T_ * H_];
__device__ float g_k[B_ * T_ * H_];
__device__ float g_v[B_ * T_ * H_];
// W fragment layout, PAIRED n-tiles:
// [half(2)][chunk(6)][hl(2)][ntp(6)][ks(4)][lane(32)][reg(4)] b32  (73728 total)
__device__ uint32_t g_Wfrag32[73728];

__device__ __forceinline__ uint32_t smem_u32(const void* p) {
    uint32_t a;
    asm("{ .reg .u64 t; cvta.to.shared.u64 t, %1; cvt.u32.u64 %0, t; }"
        : "=r"(a) : "l"(p));
    return a;
}
#define CP_ASYNC16(dst_u32, src_ptr) \
    asm volatile("cp.async.ca.shared.global [%0], [%1], 16;" \
                 :: "r"(dst_u32), "l"(src_ptr) : "memory")
#define CP_COMMIT()  asm volatile("cp.async.commit_group;" ::: "memory")
#define CP_WAIT0()   asm volatile("cp.async.wait_group 0;" ::: "memory")

__device__ __forceinline__ void hmma_bf16(float* c, const uint32_t* a, const uint32_t* b) {
    asm volatile("mma.sync.aligned.m16n8k16.row.col.f32.bf16.bf16.f32 "
        "{%0,%1,%2,%3},{%4,%5,%6,%7},{%8,%9},{%0,%1,%2,%3};"
        : "+f"(c[0]), "+f"(c[1]), "+f"(c[2]), "+f"(c[3])
        : "r"(a[0]), "r"(a[1]), "r"(a[2]), "r"(a[3]), "r"(b[0]), "r"(b[1]));
}
__device__ __forceinline__ void hmma_f16(float* c, const uint32_t* a, const uint32_t* b) {
    asm volatile("mma.sync.aligned.m16n8k16.row.col.f32.f16.f16.f32 "
        "{%0,%1,%2,%3},{%4,%5,%6,%7},{%8,%9},{%0,%1,%2,%3};"
        : "+f"(c[0]), "+f"(c[1]), "+f"(c[2]), "+f"(c[3])
        : "r"(a[0]), "r"(a[1]), "r"(a[2]), "r"(a[3]), "r"(b[0]), "r"(b[1]));
}
__device__ __forceinline__ float ex2f(float x) {
    float y;
    asm("ex2.approx.f32 %0, %1;" : "=f"(y) : "f"(x));
    return y;
}
__device__ __forceinline__ uint32_t h2exp2(uint32_t x) {
    uint32_t y;
    asm("ex2.approx.f16x2 %0, %1;" : "=r"(y) : "r"(x));
    return y;
}
// hi/lo split, bf16 (round-5 exact form)
__device__ __forceinline__ void pack_hl(float x, float y, uint32_t& hi, uint32_t& lo) {
    __nv_bfloat16 hx = __float2bfloat16(x), hy = __float2bfloat16(y);
    __nv_bfloat16 lx = __float2bfloat16(x - __bfloat162float(hx));
    __nv_bfloat16 ly = __float2bfloat16(y - __bfloat162float(hy));
    __nv_bfloat162 h = __halves2bfloat162(hx, hy);
    __nv_bfloat162 l = __halves2bfloat162(lx, ly);
    hi = *reinterpret_cast<uint32_t*>(&h);
    lo = *reinterpret_cast<uint32_t*>(&l);
}
__device__ __forceinline__ uint32_t pack_f16(float x, float y) {
    __half2 h = __floats2half2_rn(x, y);
    return *reinterpret_cast<uint32_t*>(&h);
}

// ======================= W split to PAIRED fragment layout =================
__global__ void split_w_kernel(const float* __restrict__ Wq,
                               const float* __restrict__ Wk,
                               const float* __restrict__ Wv) {
    int t = blockIdx.x * 256 + threadIdx.x;   // 36864 = 192 n x 192 k-pairs
    if (t >= 192 * 192) return;
    int n  = t / 192;
    int kp = t - n * 192;
    int k0 = kp * 2;
    int mat = n >> 6, col = n & 63;
    const float* W = (mat == 0) ? Wq : (mat == 1 ? Wk : Wv);
    float v0 = W[(size_t)k0 * 64 + col];
    float v1 = W[(size_t)(k0 + 1) * 64 + col];
    uint32_t hp, lp;
    pack_hl(v0, v1, hp, lp);

    int half  = (n >= 96) ? 1 : 0;
    int nl    = n - 96 * half;
    int nt    = nl >> 3;                      // 0..11
    int ntp   = nt >> 1;                      // pair index 0..5
    int sub   = nt & 1;
    int chunk = k0 >> 6;
    int kc    = k0 & 63;
    int ks    = kc >> 4;
    int kk    = kc & 15;
    int lane  = ((nl & 7) << 2) | ((kk >> 1) & 3);
    int reg   = sub * 2 + (kk >> 3);          // 0..3
    int idx0 = ((((((half * 6 + chunk) * 2 + 0) * 6 + ntp) * 4 + ks) * 32 + lane)) * 4 + reg;
    int idx1 = ((((((half * 6 + chunk) * 2 + 1) * 6 + ntp) * 4 + ks) * 32 + lane)) * 4 + reg;
    g_Wfrag32[idx0] = hp;
    g_Wfrag32[idx1] = lp;
}

// ======================= projection (bf16 mma.sync) =======================
// CTA tile M=128 x N=96 (per blockIdx half), warp tile 32x48:
// 8 warps = 4 warp-rows (wm: 32 M-rows) x 2 warp-cols (wn: 48 N-cols).
// Per ks: A = 4 LDS.128, B = 6 LDS.128, 36 HMMA (10 LDS / 36 HMMA).
#define SA_B32 8192
#define SB_B32 6144
#define PROJ_SMEM ((SA_B32 + SB_B32) * 4)    // 57344 B

__global__ __launch_bounds__(256, 2)
void proj_bf16_kernel(const float* __restrict__ x) {
    extern __shared__ uint32_t sm32[];
    uint32_t* sA = sm32;
    uint32_t* sB = sm32 + SA_B32;
    const uint32_t sB_smem = smem_u32(sB);

    const int tid  = threadIdx.x;
    const int lane = tid & 31;
    const int wid  = tid >> 5;
    const int wm   = wid >> 1;                // 0..3 : 32 M-rows
    const int wn   = wid & 1;                 // 0..1 : 48 N-cols
    const int mtile = blockIdx.x >> 1;
    const int half  = blockIdx.x & 1;
    const int row0  = mtile * 128;

    float acc[2][6][4];
    #pragma unroll
    for (int mt = 0; mt < 2; ++mt)
        #pragma unroll
        for (int nt = 0; nt < 6; ++nt)
            #pragma unroll
            for (int e = 0; e < 4; ++e) acc[mt][nt][e] = 0.0f;

    #pragma unroll 1
    for (int c = 0; c < 6; ++c) {
        __syncthreads();
        {
            const uint32_t* src = g_Wfrag32 + (size_t)(half * 6 + c) * SB_B32;
            #pragma unroll
            for (int j = 0; j < 6; ++j) {
                int i = tid + j * 256;
                CP_ASYNC16(sB_smem + i * 16, src + i * 4);
            }
            CP_COMMIT();
        }
        #pragma unroll
        for (int j = 0; j < 8; ++j) {
            int idx = tid + j * 256;
            int m  = idx >> 4;
            int c4 = idx & 15;
            float4 v = *reinterpret_cast<const float4*>(
                x + (size_t)(row0 + m) * C_ + c * 64 + c4 * 4);
            uint32_t hp0, lp0, hp1, lp1;
            pack_hl(v.x, v.y, hp0, lp0);
            pack_hl(v.z, v.w, hp1, lp1);
            int mt    = m >> 4;
            int ks    = c4 >> 2;
            int lane0 = ((m & 7) << 2) | (2 * (c4 & 1));
            int reg   = (c4 & 2) | ((m & 8) >> 3);
            int b0 = ((mt * 4 + ks) * 32 + lane0) * 4 + reg;
            sA[b0]                  = hp0;
            sA[b0 + 4]              = hp1;
            sA[b0 + SA_B32 / 2]     = lp0;
            sA[b0 + SA_B32 / 2 + 4] = lp1;
        }
        CP_WAIT0();
        __syncthreads();

        #pragma unroll
        for (int ks = 0; ks < 4; ++ks) {
            uint32_t af[2][2][4];
            uint32_t bf[2][6][2];
            #pragma unroll
            for (int hl = 0; hl < 2; ++hl)
                #pragma unroll
                for (int mt = 0; mt < 2; ++mt) {
                    const uint32_t* p = sA + ((((hl * 8) + wm * 2 + mt) * 4 + ks) * 32 + lane) * 4;
                    uint4 q = *reinterpret_cast<const uint4*>(p);
                    af[hl][mt][0] = q.x; af[hl][mt][1] = q.y;
                    af[hl][mt][2] = q.z; af[hl][mt][3] = q.w;
                }
            #pragma unroll
            for (int hl = 0; hl < 2; ++hl)
                #pragma unroll
                for (int ntp = 0; ntp < 3; ++ntp) {
                    const uint32_t* p = sB + ((((hl * 6) + wn * 3 + ntp) * 4 + ks) * 32 + lane) * 4;
                    uint4 q = *reinterpret_cast<const uint4*>(p);
                    bf[hl][2 * ntp][0]     = q.x; bf[hl][2 * ntp][1]     = q.y;
                    bf[hl][2 * ntp + 1][0] = q.z; bf[hl][2 * ntp + 1][1] = q.w;
                }
            #pragma unroll
            for (int mt = 0; mt < 2; ++mt)
                #pragma unroll
                for (int nt = 0; nt < 6; ++nt)
                    hmma_bf16(acc[mt][nt], af[0][mt], bf[0][nt]);
            #pragma unroll
            for (int mt = 0; mt < 2; ++mt)
                #pragma unroll
                for (int nt = 0; nt < 6; ++nt)
                    hmma_bf16(acc[mt][nt], af[0][mt], bf[1][nt]);
            #pragma unroll
            for (int mt = 0; mt < 2; ++mt)
                #pragma unroll
                for (int nt = 0; nt < 6; ++nt)
                    hmma_bf16(acc[mt][nt], af[1][mt], bf[0][nt]);
        }
    }

    // ---- epilogue: write q/k/v ----
    #pragma unroll
    for (int mt = 0; mt < 2; ++mt) {
        #pragma unroll
        for (int nt = 0; nt < 6; ++nt) {
            int n0  = half * 96 + wn * 48 + nt * 8;
            int mat = n0 >> 6;
            int col = (n0 & 63) + (lane & 3) * 2;
            float* O = (mat == 0) ? g_q : (mat == 1 ? g_k : g_v);
            int grow = row0 + wm * 32 + mt * 16 + (lane >> 2);
            *reinterpret_cast<float2*>(&O[(size_t)grow * 64 + col]) =
                make_float2(acc[mt][nt][0], acc[mt][nt][1]);
            *reinterpret_cast<float2*>(&O[(size_t)(grow + 8) * 64 + col]) =
                make_float2(acc[mt][nt][2], acc[mt][nt][3]);
        }
    }
}

// ======================= attention (round-14 exact) ======================
#define ATTK_B32 8192
#define ATTV_B32 9216
#define ATTN_SMEM ((2 * ATTK_B32 + ATTV_B32) * 4)   // 101376 B

__global__ __launch_bounds__(256, 2)
void attn_mma_kernel(float* __restrict__ out) {
    extern __shared__ uint32_t am32[];
    uint32_t* sKhi = am32;
    uint32_t* sKlo = am32 + ATTK_B32;
    uint32_t* sV   = am32 + 2 * ATTK_B32;

    const int bb   = blockIdx.x;
    const int tid  = threadIdx.x;
    const int lane = tid & 31;
    const int w    = tid >> 5;                 // 0..7
    const float* qp = g_q + (size_t)bb * T_ * H_;
    const float* kp = g_k + (size_t)bb * T_ * H_;
    const float* vp = g_v + (size_t)bb * T_ * H_;
    float* outp = out + (size_t)bb * T_ * H_;

    #pragma unroll 4
    for (int it = 0; it < 32; ++it) {
        int slot = w + it * 8;
        int reg = slot & 1, nt = (slot >> 1) & 7, ks = (slot >> 4) & 3, j = slot >> 6;
        int addr = (slot >> 1) * 64 + lane * 2 + reg;
        {
            int s = j * 64 + nt * 8 + (lane >> 2);
            int h = ks * 16 + (lane & 3) * 2 + reg * 8;
            float2 kv = *reinterpret_cast<const float2*>(kp + s * 64 + h);
            uint32_t hp, lp;
            pack_hl(kv.x, kv.y, hp, lp);
            sKhi[addr] = hp; sKlo[addr] = lp;
        }
        {
            int n  = nt * 8 + (lane >> 2);
            int s0 = j * 64 + ks * 16 + (lane & 3) * 2 + reg * 8;
            float v0 = vp[s0 * 64 + n];
            float v1 = vp[(s0 + 1) * 64 + n];
            int jk = j * 4 + ks;
            sV[(jk * 9 + nt) * 64 + lane * 2 + reg] = pack_f16(v0, v1);
        }
    }
    #pragma unroll
    for (int i = tid; i < 1024; i += 256) {
        int jk = i >> 6;
        sV[(jk * 9 + 8) * 64 + (i & 63)] = 0x3C003C00u;   // (1.0h, 1.0h)
    }
    __syncthreads();

    #pragma unroll 1
    for (int hf = 0; hf < 2; ++hf) {
        const int t = hf ? (15 - w) : w;
        const int jmax = t >> 2;
        const int r0 = t * 16 + (lane >> 2);

        uint32_t qh[4][4], ql[4][4];
        #pragma unroll
        for (int ks = 0; ks < 4; ++ks) {
            int k0 = ks * 16 + (lane & 3) * 2;
            float2 v00 = *reinterpret_cast<const float2*>(qp + r0 * 64 + k0);
            float2 v10 = *reinterpret_cast<const float2*>(qp + (r0 + 8) * 64 + k0);
            float2 v01 = *reinterpret_cast<const float2*>(qp + r0 * 64 + k0 + 8);
            float2 v11 = *reinterpret_cast<const float2*>(qp + (r0 + 8) * 64 + k0 + 8);
            pack_hl(v00.x * QK_SCALE, v00.y * QK_SCALE, qh[ks][0], ql[ks][0]);
            pack_hl(v10.x * QK_SCALE, v10.y * QK_SCALE, qh[ks][1], ql[ks][1]);
            pack_hl(v01.x * QK_SCALE, v01.y * QK_SCALE, qh[ks][2], ql[ks][2]);
            pack_hl(v11.x * QK_SCALE, v11.y * QK_SCALE, qh[ks][3], ql[ks][3]);
        }

        float o[9][4];
        #pragma unroll
        for (int nt = 0; nt < 9; ++nt)
            #pragma unroll
            for (int e = 0; e < 4; ++e) o[nt][e] = 0.0f;
        float m0 = -1.0e30f, m1 = -1.0e30f;

        #pragma unroll 1
        for (int j = 0; j <= jmax; ++j) {
            float s[8][4];
            #pragma unroll
            for (int nt = 0; nt < 8; ++nt)
                #pragma unroll
                for (int e = 0; e < 4; ++e) s[nt][e] = 0.0f;
            #pragma unroll
            for (int ks = 0; ks < 4; ++ks) {
                const uint2* kh = reinterpret_cast<const uint2*>(sKhi) + ((j * 4 + ks) * 8) * 32 + lane;
                const uint2* kl = reinterpret_cast<const uint2*>(sKlo) + ((j * 4 + ks) * 8) * 32 + lane;
                #pragma unroll
                for (int nt = 0; nt < 8; ++nt) {
                    uint2 bh2 = kh[nt * 32], bl2 = kl[nt * 32];
                    uint32_t bh[2] = {bh2.x, bh2.y};
                    uint32_t bl[2] = {bl2.x, bl2.y};
                    hmma_bf16(s[nt], qh[ks], bh);
                    hmma_bf16(s[nt], qh[ks], bl);
                    hmma_bf16(s[nt], ql[ks], bh);
                }
            }
            if (j == jmax) {
                int cb = 64 * j + (lane & 3) * 2;
                #pragma unroll
                for (int nt = 0; nt < 8; ++nt) {
                    int c = cb + nt * 8;
                    if (c > r0)         s[nt][0] = -1.0e30f;
                    if (c + 1 > r0)     s[nt][1] = -1.0e30f;
                    if (c > r0 + 8)     s[nt][2] = -1.0e30f;
                    if (c + 1 > r0 + 8) s[nt][3] = -1.0e30f;
                }
            }
            float bm0 = -1.0e30f, bm1 = -1.0e30f;
            #pragma unroll
            for (int nt = 0; nt < 8; ++nt) {
                bm0 = fmaxf(bm0, fmaxf(s[nt][0], s[nt][1]));
                bm1 = fmaxf(bm1, fmaxf(s[nt][2], s[nt][3]));
            }
            bm0 = fmaxf(bm0, __shfl_xor_sync(0xffffffffu, bm0, 1));
            bm0 = fmaxf(bm0, __shfl_xor_sync(0xffffffffu, bm0, 2));
            bm1 = fmaxf(bm1, __shfl_xor_sync(0xffffffffu, bm1, 1));
            bm1 = fmaxf(bm1, __shfl_xor_sync(0xffffffffu, bm1, 2));
            float mn0 = fmaxf(m0, bm0), mn1 = fmaxf(m1, bm1);
            float sc0 = ex2f(m0 - mn0), sc1 = ex2f(m1 - mn1);
            m0 = mn0; m1 = mn1;
            uint32_t p2[8][2];
            #pragma unroll
            for (int nt = 0; nt < 8; ++nt) {
                p2[nt][0] = h2exp2(pack_f16(s[nt][0] - mn0, s[nt][1] - mn0));
                p2[nt][1] = h2exp2(pack_f16(s[nt][2] - mn1, s[nt][3] - mn1));
            }
            #pragma unroll
            for (int nt = 0; nt < 9; ++nt) {
                o[nt][0] *= sc0; o[nt][1] *= sc0;
                o[nt][2] *= sc1; o[nt][3] *= sc1;
            }
            #pragma unroll
            for (int kk = 0; kk < 4; ++kk) {
                uint32_t pa[4];
                pa[0] = p2[2 * kk][0];
                pa[1] = p2[2 * kk][1];
                pa[2] = p2[2 * kk + 1][0];
                pa[3] = p2[2 * kk + 1][1];
                const uint2* vh = reinterpret_cast<const uint2*>(sV) + ((j * 4 + kk) * 9) * 32 + lane;
                #pragma unroll
                for (int nt = 0; nt < 9; ++nt) {
                    uint2 bh2 = vh[nt * 32];
                    uint32_t bh[2] = {bh2.x, bh2.y};
                    hmma_f16(o[nt], pa, bh);
                }
            }
        }

        float inv0 = 1.0f / o[8][0], inv1 = 1.0f / o[8][2];
        #pragma unroll
        for (int nt = 0; nt < 8; ++nt) {
            int col = nt * 8 + (lane & 3) * 2;
            *reinterpret_cast<float2*>(outp + r0 * 64 + col) =
                make_float2(o[nt][0] * inv0, o[nt][1] * inv0);
            *reinterpret_cast<float2*>(outp + (r0 + 8) * 64 + col) =
                make_float2(o[nt][2] * inv1, o[nt][3] * inv1);
        }
    }
}

// ---------------------------------------------------------------------------
extern "C" void kernel_launch(void* const* d_in, const int* in_sizes, int n_in,
                              void* d_out, int out_size) {
    const float* x  = (const float*)d_in[0];
    const float* Wq = (const float*)d_in[1];
    const float* Wk = (const float*)d_in[2];
    const float* Wv = (const float*)d_in[3];
    float* out = (float*)d_out;

    cudaFuncSetAttribute(proj_bf16_kernel, cudaFuncAttributeMaxDynamicSharedMemorySize, PROJ_SMEM);
    cudaFuncSetAttribute(attn_mma_kernel, cudaFuncAttributeMaxDynamicSharedMemorySize, ATTN_SMEM);

    split_w_kernel<<<144, 256>>>(Wq, Wk, Wv);
    proj_bf16_kernel<<<2048, 256, PROJ_SMEM>>>(x);
    attn_mma_kernel<<<B_, 256, ATTN_SMEM>>>(out);
}

// round 17
// speedup vs baseline: 1.1639x; 1.0151x over previous
#include <cuda_runtime.h>
#include <cuda_bf16.h>
#include <cuda_fp16.h>
#include <cstdint>

#define B_ 512
#define T_ 256
#define C_ 384
#define H_ 64
#define SCALE_F 19.595917942265423f
#define QK_SCALE (SCALE_F * 1.4426950408889634f)   // fold log2(e) -> use ex2

// scratch: q,k,v projections [B,T,H] fp32
__device__ float g_q[B_ * T_ * H_];
__device__ float g_k[B_ * T_ * H_];
__device__ float g_v[B_ * T_ * H_];
// W fragment layout, PAIRED n-tiles:
// [half(2)][chunk(6)][hl(2)][ntp(6)][ks(4)][lane(32)][reg(4)] b32  (73728 total)
__device__ uint32_t g_Wfrag32[73728];

__device__ __forceinline__ uint32_t smem_u32(const void* p) {
    uint32_t a;
    asm("{ .reg .u64 t; cvta.to.shared.u64 t, %1; cvt.u32.u64 %0, t; }"
        : "=r"(a) : "l"(p));
    return a;
}
#define CP_ASYNC16(dst_u32, src_ptr) \
    asm volatile("cp.async.ca.shared.global [%0], [%1], 16;" \
                 :: "r"(dst_u32), "l"(src_ptr) : "memory")
#define CP_COMMIT()  asm volatile("cp.async.commit_group;" ::: "memory")
#define CP_WAIT0()   asm volatile("cp.async.wait_group 0;" ::: "memory")

__device__ __forceinline__ void hmma_bf16(float* c, const uint32_t* a, const uint32_t* b) {
    asm volatile("mma.sync.aligned.m16n8k16.row.col.f32.bf16.bf16.f32 "
        "{%0,%1,%2,%3},{%4,%5,%6,%7},{%8,%9},{%0,%1,%2,%3};"
        : "+f"(c[0]), "+f"(c[1]), "+f"(c[2]), "+f"(c[3])
        : "r"(a[0]), "r"(a[1]), "r"(a[2]), "r"(a[3]), "r"(b[0]), "r"(b[1]));
}
__device__ __forceinline__ void hmma_f16(float* c, const uint32_t* a, const uint32_t* b) {
    asm volatile("mma.sync.aligned.m16n8k16.row.col.f32.f16.f16.f32 "
        "{%0,%1,%2,%3},{%4,%5,%6,%7},{%8,%9},{%0,%1,%2,%3};"
        : "+f"(c[0]), "+f"(c[1]), "+f"(c[2]), "+f"(c[3])
        : "r"(a[0]), "r"(a[1]), "r"(a[2]), "r"(a[3]), "r"(b[0]), "r"(b[1]));
}
__device__ __forceinline__ float ex2f(float x) {
    float y;
    asm("ex2.approx.f32 %0, %1;" : "=f"(y) : "f"(x));
    return y;
}
__device__ __forceinline__ uint32_t h2exp2(uint32_t x) {
    uint32_t y;
    asm("ex2.approx.f16x2 %0, %1;" : "=r"(y) : "r"(x));
    return y;
}
// hi/lo split, bf16 (round-5 exact form)
__device__ __forceinline__ void pack_hl(float x, float y, uint32_t& hi, uint32_t& lo) {
    __nv_bfloat16 hx = __float2bfloat16(x), hy = __float2bfloat16(y);
    __nv_bfloat16 lx = __float2bfloat16(x - __bfloat162float(hx));
    __nv_bfloat16 ly = __float2bfloat16(y - __bfloat162float(hy));
    __nv_bfloat162 h = __halves2bfloat162(hx, hy);
    __nv_bfloat162 l = __halves2bfloat162(lx, ly);
    hi = *reinterpret_cast<uint32_t*>(&h);
    lo = *reinterpret_cast<uint32_t*>(&l);
}
__device__ __forceinline__ uint32_t pack_f16(float x, float y) {
    __half2 h = __floats2half2_rn(x, y);
    return *reinterpret_cast<uint32_t*>(&h);
}

// ======================= W split to PAIRED fragment layout =================
__global__ void split_w_kernel(const float* __restrict__ Wq,
                               const float* __restrict__ Wk,
                               const float* __restrict__ Wv) {
    int t = blockIdx.x * 256 + threadIdx.x;   // 36864 = 192 n x 192 k-pairs
    if (t >= 192 * 192) return;
    int n  = t / 192;
    int kp = t - n * 192;
    int k0 = kp * 2;
    int mat = n >> 6, col = n & 63;
    const float* W = (mat == 0) ? Wq : (mat == 1 ? Wk : Wv);
    float v0 = W[(size_t)k0 * 64 + col];
    float v1 = W[(size_t)(k0 + 1) * 64 + col];
    uint32_t hp, lp;
    pack_hl(v0, v1, hp, lp);

    int half  = (n >= 96) ? 1 : 0;
    int nl    = n - 96 * half;
    int nt    = nl >> 3;                      // 0..11
    int ntp   = nt >> 1;                      // pair index 0..5
    int sub   = nt & 1;
    int chunk = k0 >> 6;
    int kc    = k0 & 63;
    int ks    = kc >> 4;
    int kk    = kc & 15;
    int lane  = ((nl & 7) << 2) | ((kk >> 1) & 3);
    int reg   = sub * 2 + (kk >> 3);          // 0..3
    int idx0 = ((((((half * 6 + chunk) * 2 + 0) * 6 + ntp) * 4 + ks) * 32 + lane)) * 4 + reg;
    int idx1 = ((((((half * 6 + chunk) * 2 + 1) * 6 + ntp) * 4 + ks) * 32 + lane)) * 4 + reg;
    g_Wfrag32[idx0] = hp;
    g_Wfrag32[idx1] = lp;
}

// ======================= projection (round-16 exact) ======================
#define SA_B32 8192
#define SB_B32 6144
#define PROJ_SMEM ((SA_B32 + SB_B32) * 4)    // 57344 B

__global__ __launch_bounds__(256, 2)
void proj_bf16_kernel(const float* __restrict__ x) {
    extern __shared__ uint32_t sm32[];
    uint32_t* sA = sm32;
    uint32_t* sB = sm32 + SA_B32;
    const uint32_t sB_smem = smem_u32(sB);

    const int tid  = threadIdx.x;
    const int lane = tid & 31;
    const int wid  = tid >> 5;
    const int wm   = wid >> 1;                // 0..3 : 32 M-rows
    const int wn   = wid & 1;                 // 0..1 : 48 N-cols
    const int mtile = blockIdx.x >> 1;
    const int half  = blockIdx.x & 1;
    const int row0  = mtile * 128;

    float acc[2][6][4];
    #pragma unroll
    for (int mt = 0; mt < 2; ++mt)
        #pragma unroll
        for (int nt = 0; nt < 6; ++nt)
            #pragma unroll
            for (int e = 0; e < 4; ++e) acc[mt][nt][e] = 0.0f;

    #pragma unroll 1
    for (int c = 0; c < 6; ++c) {
        __syncthreads();
        {
            const uint32_t* src = g_Wfrag32 + (size_t)(half * 6 + c) * SB_B32;
            #pragma unroll
            for (int j = 0; j < 6; ++j) {
                int i = tid + j * 256;
                CP_ASYNC16(sB_smem + i * 16, src + i * 4);
            }
            CP_COMMIT();
        }
        #pragma unroll
        for (int j = 0; j < 8; ++j) {
            int idx = tid + j * 256;
            int m  = idx >> 4;
            int c4 = idx & 15;
            float4 v = *reinterpret_cast<const float4*>(
                x + (size_t)(row0 + m) * C_ + c * 64 + c4 * 4);
            uint32_t hp0, lp0, hp1, lp1;
            pack_hl(v.x, v.y, hp0, lp0);
            pack_hl(v.z, v.w, hp1, lp1);
            int mt    = m >> 4;
            int ks    = c4 >> 2;
            int lane0 = ((m & 7) << 2) | (2 * (c4 & 1));
            int reg   = (c4 & 2) | ((m & 8) >> 3);
            int b0 = ((mt * 4 + ks) * 32 + lane0) * 4 + reg;
            sA[b0]                  = hp0;
            sA[b0 + 4]              = hp1;
            sA[b0 + SA_B32 / 2]     = lp0;
            sA[b0 + SA_B32 / 2 + 4] = lp1;
        }
        CP_WAIT0();
        __syncthreads();

        #pragma unroll
        for (int ks = 0; ks < 4; ++ks) {
            uint32_t af[2][2][4];
            uint32_t bf[2][6][2];
            #pragma unroll
            for (int hl = 0; hl < 2; ++hl)
                #pragma unroll
                for (int mt = 0; mt < 2; ++mt) {
                    const uint32_t* p = sA + ((((hl * 8) + wm * 2 + mt) * 4 + ks) * 32 + lane) * 4;
                    uint4 q = *reinterpret_cast<const uint4*>(p);
                    af[hl][mt][0] = q.x; af[hl][mt][1] = q.y;
                    af[hl][mt][2] = q.z; af[hl][mt][3] = q.w;
                }
            #pragma unroll
            for (int hl = 0; hl < 2; ++hl)
                #pragma unroll
                for (int ntp = 0; ntp < 3; ++ntp) {
                    const uint32_t* p = sB + ((((hl * 6) + wn * 3 + ntp) * 4 + ks) * 32 + lane) * 4;
                    uint4 q = *reinterpret_cast<const uint4*>(p);
                    bf[hl][2 * ntp][0]     = q.x; bf[hl][2 * ntp][1]     = q.y;
                    bf[hl][2 * ntp + 1][0] = q.z; bf[hl][2 * ntp + 1][1] = q.w;
                }
            #pragma unroll
            for (int mt = 0; mt < 2; ++mt)
                #pragma unroll
                for (int nt = 0; nt < 6; ++nt)
                    hmma_bf16(acc[mt][nt], af[0][mt], bf[0][nt]);
            #pragma unroll
            for (int mt = 0; mt < 2; ++mt)
                #pragma unroll
                for (int nt = 0; nt < 6; ++nt)
                    hmma_bf16(acc[mt][nt], af[0][mt], bf[1][nt]);
            #pragma unroll
            for (int mt = 0; mt < 2; ++mt)
                #pragma unroll
                for (int nt = 0; nt < 6; ++nt)
                    hmma_bf16(acc[mt][nt], af[1][mt], bf[0][nt]);
        }
    }

    #pragma unroll
    for (int mt = 0; mt < 2; ++mt) {
        #pragma unroll
        for (int nt = 0; nt < 6; ++nt) {
            int n0  = half * 96 + wn * 48 + nt * 8;
            int mat = n0 >> 6;
            int col = (n0 & 63) + (lane & 3) * 2;
            float* O = (mat == 0) ? g_q : (mat == 1 ? g_k : g_v);
            int grow = row0 + wm * 32 + mt * 16 + (lane >> 2);
            *reinterpret_cast<float2*>(&O[(size_t)grow * 64 + col]) =
                make_float2(acc[mt][nt][0], acc[mt][nt][1]);
            *reinterpret_cast<float2*>(&O[(size_t)(grow + 8) * 64 + col]) =
                make_float2(acc[mt][nt][2], acc[mt][nt][3]);
        }
    }
}

// ======================= attention (paired K/V fragments) ================
// QK bf16 3-pass, PV fp16 + constant-ones denominator column.
// K/V n-tiles PAIRED in smem: [jk(16)][ntp(4)][lane(32)][reg(4)] b32 each
// -> QK: 8 LDS.128 per (j,ks) (was 16 LDS.64); PV: 4 LDS.128 per (j,kk)
// (was 9 LDS.64; ones column is immediate 0x3C003C00, no load/store at all).
#define ATTK_B32 8192
#define ATTV_B32 8192
#define ATTN_SMEM ((2 * ATTK_B32 + ATTV_B32) * 4)   // 98304 B

__global__ __launch_bounds__(256, 2)
void attn_mma_kernel(float* __restrict__ out) {
    extern __shared__ uint32_t am32[];
    uint32_t* sKhi = am32;
    uint32_t* sKlo = am32 + ATTK_B32;
    uint32_t* sV   = am32 + 2 * ATTK_B32;

    const int bb   = blockIdx.x;
    const int tid  = threadIdx.x;
    const int lane = tid & 31;
    const int w    = tid >> 5;                 // 0..7
    const float* qp = g_q + (size_t)bb * T_ * H_;
    const float* kp = g_k + (size_t)bb * T_ * H_;
    const float* vp = g_v + (size_t)bb * T_ * H_;
    float* outp = out + (size_t)bb * T_ * H_;

    // ---- prep: K -> bf16 hi/lo, V -> fp16, paired-tile addresses ----
    #pragma unroll 4
    for (int it = 0; it < 32; ++it) {
        int slot = w + it * 8;                 // 0..255 = [j4][ks4][nt8][reg2]
        int reg = slot & 1, nt = (slot >> 1) & 7, ks = (slot >> 4) & 3, j = slot >> 6;
        int jk   = j * 4 + ks;
        int ntp  = nt >> 1;
        int sub  = nt & 1;
        int addr = ((jk * 4 + ntp) * 32 + lane) * 4 + sub * 2 + reg;
        {   // K: n = key pos, k = h
            int s = j * 64 + nt * 8 + (lane >> 2);
            int h = ks * 16 + (lane & 3) * 2 + reg * 8;
            float2 kv = *reinterpret_cast<const float2*>(kp + s * 64 + h);
            uint32_t hp, lp;
            pack_hl(kv.x, kv.y, hp, lp);
            sKhi[addr] = hp; sKlo[addr] = lp;
        }
        {   // V: n = head col, k = key pos within block (fp16)
            int n  = nt * 8 + (lane >> 2);
            int s0 = j * 64 + ks * 16 + (lane & 3) * 2 + reg * 8;
            float v0 = vp[s0 * 64 + n];
            float v1 = vp[(s0 + 1) * 64 + n];
            sV[addr] = pack_f16(v0, v1);
        }
    }
    __syncthreads();

    #pragma unroll 1
    for (int hf = 0; hf < 2; ++hf) {
        const int t = hf ? (15 - w) : w;
        const int jmax = t >> 2;
        const int r0 = t * 16 + (lane >> 2);

        uint32_t qh[4][4], ql[4][4];
        #pragma unroll
        for (int ks = 0; ks < 4; ++ks) {
            int k0 = ks * 16 + (lane & 3) * 2;
            float2 v00 = *reinterpret_cast<const float2*>(qp + r0 * 64 + k0);
            float2 v10 = *reinterpret_cast<const float2*>(qp + (r0 + 8) * 64 + k0);
            float2 v01 = *reinterpret_cast<const float2*>(qp + r0 * 64 + k0 + 8);
            float2 v11 = *reinterpret_cast<const float2*>(qp + (r0 + 8) * 64 + k0 + 8);
            pack_hl(v00.x * QK_SCALE, v00.y * QK_SCALE, qh[ks][0], ql[ks][0]);
            pack_hl(v10.x * QK_SCALE, v10.y * QK_SCALE, qh[ks][1], ql[ks][1]);
            pack_hl(v01.x * QK_SCALE, v01.y * QK_SCALE, qh[ks][2], ql[ks][2]);
            pack_hl(v11.x * QK_SCALE, v11.y * QK_SCALE, qh[ks][3], ql[ks][3]);
        }

        float o[9][4];
        #pragma unroll
        for (int nt = 0; nt < 9; ++nt)
            #pragma unroll
            for (int e = 0; e < 4; ++e) o[nt][e] = 0.0f;
        float m0 = -1.0e30f, m1 = -1.0e30f;

        #pragma unroll 1
        for (int j = 0; j <= jmax; ++j) {
            // ---- S = Q K^T (bf16 3-pass, paired LDS.128) ----
            float s[8][4];
            #pragma unroll
            for (int nt = 0; nt < 8; ++nt)
                #pragma unroll
                for (int e = 0; e < 4; ++e) s[nt][e] = 0.0f;
            #pragma unroll
            for (int ks = 0; ks < 4; ++ks) {
                const uint4* kh4 = reinterpret_cast<const uint4*>(sKhi) + ((j * 4 + ks) * 4) * 32 + lane;
                const uint4* kl4 = reinterpret_cast<const uint4*>(sKlo) + ((j * 4 + ks) * 4) * 32 + lane;
                #pragma unroll
                for (int ntp = 0; ntp < 4; ++ntp) {
                    uint4 qh4 = kh4[ntp * 32];
                    uint4 ql4 = kl4[ntp * 32];
                    uint32_t bh0[2] = {qh4.x, qh4.y};
                    uint32_t bh1[2] = {qh4.z, qh4.w};
                    uint32_t bl0[2] = {ql4.x, ql4.y};
                    uint32_t bl1[2] = {ql4.z, ql4.w};
                    hmma_bf16(s[2 * ntp],     qh[ks], bh0);
                    hmma_bf16(s[2 * ntp],     qh[ks], bl0);
                    hmma_bf16(s[2 * ntp],     ql[ks], bh0);
                    hmma_bf16(s[2 * ntp + 1], qh[ks], bh1);
                    hmma_bf16(s[2 * ntp + 1], qh[ks], bl1);
                    hmma_bf16(s[2 * ntp + 1], ql[ks], bh1);
                }
            }
            // ---- causal mask on diagonal block ----
            if (j == jmax) {
                int cb = 64 * j + (lane & 3) * 2;
                #pragma unroll
                for (int nt = 0; nt < 8; ++nt) {
                    int c = cb + nt * 8;
                    if (c > r0)         s[nt][0] = -1.0e30f;
                    if (c + 1 > r0)     s[nt][1] = -1.0e30f;
                    if (c > r0 + 8)     s[nt][2] = -1.0e30f;
                    if (c + 1 > r0 + 8) s[nt][3] = -1.0e30f;
                }
            }
            // ---- online softmax: max (quad reduction) ----
            float bm0 = -1.0e30f, bm1 = -1.0e30f;
            #pragma unroll
            for (int nt = 0; nt < 8; ++nt) {
                bm0 = fmaxf(bm0, fmaxf(s[nt][0], s[nt][1]));
                bm1 = fmaxf(bm1, fmaxf(s[nt][2], s[nt][3]));
            }
            bm0 = fmaxf(bm0, __shfl_xor_sync(0xffffffffu, bm0, 1));
            bm0 = fmaxf(bm0, __shfl_xor_sync(0xffffffffu, bm0, 2));
            bm1 = fmaxf(bm1, __shfl_xor_sync(0xffffffffu, bm1, 1));
            bm1 = fmaxf(bm1, __shfl_xor_sync(0xffffffffu, bm1, 2));
            float mn0 = fmaxf(m0, bm0), mn1 = fmaxf(m1, bm1);
            float sc0 = ex2f(m0 - mn0), sc1 = ex2f(m1 - mn1);
            m0 = mn0; m1 = mn1;
            // ---- P = exp2(S - m) in fp16x2, mma-packed ----
            uint32_t p2[8][2];
            #pragma unroll
            for (int nt = 0; nt < 8; ++nt) {
                p2[nt][0] = h2exp2(pack_f16(s[nt][0] - mn0, s[nt][1] - mn0));
                p2[nt][1] = h2exp2(pack_f16(s[nt][2] - mn1, s[nt][3] - mn1));
            }
            // ---- rescale O (incl. denominator column o[8]) ----
            #pragma unroll
            for (int nt = 0; nt < 9; ++nt) {
                o[nt][0] *= sc0; o[nt][1] *= sc0;
                o[nt][2] *= sc1; o[nt][3] *= sc1;
            }
            // ---- O += P V (paired LDS.128; ones column = constant) ----
            #pragma unroll
            for (int kk = 0; kk < 4; ++kk) {
                uint32_t pa[4];
                pa[0] = p2[2 * kk][0];
                pa[1] = p2[2 * kk][1];
                pa[2] = p2[2 * kk + 1][0];
                pa[3] = p2[2 * kk + 1][1];
                const uint4* vh4 = reinterpret_cast<const uint4*>(sV) + ((j * 4 + kk) * 4) * 32 + lane;
                #pragma unroll
                for (int ntp = 0; ntp < 4; ++ntp) {
                    uint4 vv = vh4[ntp * 32];
                    uint32_t b0[2] = {vv.x, vv.y};
                    uint32_t b1[2] = {vv.z, vv.w};
                    hmma_f16(o[2 * ntp],     pa, b0);
                    hmma_f16(o[2 * ntp + 1], pa, b1);
                }
                uint32_t bones[2] = {0x3C003C00u, 0x3C003C00u};
                hmma_f16(o[8], pa, bones);
            }
        }

        // ---- epilogue (denominator from ones column) ----
        float inv0 = 1.0f / o[8][0], inv1 = 1.0f / o[8][2];
        #pragma unroll
        for (int nt = 0; nt < 8; ++nt) {
            int col = nt * 8 + (lane & 3) * 2;
            *reinterpret_cast<float2*>(outp + r0 * 64 + col) =
                make_float2(o[nt][0] * inv0, o[nt][1] * inv0);
            *reinterpret_cast<float2*>(outp + (r0 + 8) * 64 + col) =
                make_float2(o[nt][2] * inv1, o[nt][3] * inv1);
        }
    }
}

// ---------------------------------------------------------------------------
extern "C" void kernel_launch(void* const* d_in, const int* in_sizes, int n_in,
                              void* d_out, int out_size) {
    const float* x  = (const float*)d_in[0];
    const float* Wq = (const float*)d_in[1];
    const float* Wk = (const float*)d_in[2];
    const float* Wv = (const float*)d_in[3];
    float* out = (float*)d_out;

    cudaFuncSetAttribute(proj_bf16_kernel, cudaFuncAttributeMaxDynamicSharedMemorySize, PROJ_SMEM);
    cudaFuncSetAttribute(attn_mma_kernel, cudaFuncAttributeMaxDynamicSharedMemorySize, ATTN_SMEM);

    split_w_kernel<<<144, 256>>>(Wq, Wk, Wv);
    proj_bf16_kernel<<<2048, 256, PROJ_SMEM>>>(x);
    attn_mma_kernel<<<B_, 256, ATTN_SMEM>>>(out);
}